// round 1
// baseline (speedup 1.0000x reference)
#include <cuda_runtime.h>

#define EPS      1e-4f
#define FRAMES   4000
#define NV4      1000        // FRAMES / 4
#define THREADS  256
#define CPT      16          // elements per thread (250 active threads * 16 = 4000)

__global__ __launch_bounds__(THREADS)
void cumnorm_kernel(const float* __restrict__ x, float* __restrict__ out)
{
    __shared__ float4 buf[NV4];          // 16 KB row staging (in/out reuse)
    __shared__ float2 warp_sums[8];      // per-warp (sum, sumsq) totals

    const int row = blockIdx.x;
    const float4* __restrict__ xin  = reinterpret_cast<const float4*>(x)   + (size_t)row * NV4;
    float4*       __restrict__ xout = reinterpret_cast<float4*>(out)       + (size_t)row * NV4;

    const int tid  = threadIdx.x;
    const int lane = tid & 31;
    const int warp = tid >> 5;

    // ---- stage in (coalesced float4) ----
    #pragma unroll
    for (int i = tid; i < NV4; i += THREADS) buf[i] = xin[i];
    __syncthreads();

    // ---- pass 1: per-thread partials over contiguous segment (kept in regs) ----
    float r[CPT];
    const int base4  = tid * (CPT / 4);
    const bool active = (base4 < NV4);

    float s = 0.f, q = 0.f;
    if (active) {
        #pragma unroll
        for (int j = 0; j < CPT / 4; ++j) {
            float4 v = buf[base4 + j];
            r[4*j+0] = v.x; r[4*j+1] = v.y; r[4*j+2] = v.z; r[4*j+3] = v.w;
        }
        #pragma unroll
        for (int j = 0; j < CPT; ++j) {
            s += r[j];
            q  = fmaf(r[j], r[j], q);
        }
    }

    // ---- block scan of (s, q): warp shuffle scan + warp-total scan ----
    float is = s, iq = q;
    #pragma unroll
    for (int d = 1; d < 32; d <<= 1) {
        float ts = __shfl_up_sync(0xffffffffu, is, d);
        float tq = __shfl_up_sync(0xffffffffu, iq, d);
        if (lane >= d) { is += ts; iq += tq; }
    }
    if (lane == 31) warp_sums[warp] = make_float2(is, iq);
    __syncthreads();

    if (warp == 0) {
        float ws = (lane < 8) ? warp_sums[lane].x : 0.f;
        float wq = (lane < 8) ? warp_sums[lane].y : 0.f;
        #pragma unroll
        for (int d = 1; d < 8; d <<= 1) {
            float ts = __shfl_up_sync(0xffffffffu, ws, d);
            float tq = __shfl_up_sync(0xffffffffu, wq, d);
            if (lane >= d) { ws += ts; wq += tq; }
        }
        if (lane < 8) warp_sums[lane] = make_float2(ws, wq);
    }
    __syncthreads();

    // exclusive prefix (over all elements preceding this thread's segment)
    float ps = ((warp > 0) ? warp_sums[warp - 1].x : 0.f) + (is - s);
    float pq = ((warp > 0) ? warp_sums[warp - 1].y : 0.f) + (iq - q);

    // ---- pass 2: normalize.  out = (c*x - s) * rsqrt(c*q - s^2 + eps*c^2) ----
    if (active) {
        float c = (float)(tid * CPT);
        #pragma unroll
        for (int j = 0; j < CPT; ++j) {
            float xv = r[j];
            ps += xv;
            pq  = fmaf(xv, xv, pq);
            c  += 1.f;
            float ecc = EPS * c * c;
            float den = fmaf(c, pq, fmaf(-ps, ps, ecc));   // c*q - s*s + eps*c*c
            float num = fmaf(c, xv, -ps);                  // c*x - s
            r[j] = num * rsqrtf(den);
        }
        #pragma unroll
        for (int j = 0; j < CPT / 4; ++j)
            buf[base4 + j] = make_float4(r[4*j+0], r[4*j+1], r[4*j+2], r[4*j+3]);
    }
    __syncthreads();

    // ---- stage out (coalesced float4) ----
    #pragma unroll
    for (int i = tid; i < NV4; i += THREADS) xout[i] = buf[i];
}

extern "C" void kernel_launch(void* const* d_in, const int* in_sizes, int n_in,
                              void* d_out, int out_size)
{
    const float* x = (const float*)d_in[0];
    float* out     = (float*)d_out;
    const int rows = in_sizes[0] / FRAMES;   // 32*512 = 16384
    cumnorm_kernel<<<rows, THREADS>>>(x, out);
}

// round 5
// speedup vs baseline: 1.3783x; 1.3783x over previous
#include <cuda_runtime.h>

#define EPS      1e-4f
#define FRAMES   4000
#define THREADS  256
#define TILE     (THREADS * 4)        // 1024 elements per tile
#define NTILES   4                    // 4 * 1024 = 4096 >= 4000
#define NWARPS   (THREADS / 32)

__global__ __launch_bounds__(THREADS)
void cumnorm_kernel(const float* __restrict__ x, float* __restrict__ out)
{
    __shared__ float2 wsum[NWARPS];   // per-warp inclusive (sum, sumsq)

    const int tid  = threadIdx.x;
    const int lane = tid & 31;
    const int warp = tid >> 5;

    const size_t rowoff = (size_t)blockIdx.x * FRAMES;
    const float* __restrict__ xin  = x   + rowoff;
    float*       __restrict__ xout = out + rowoff;

    // ---- issue ALL loads up front (coalesced float4, MLP=4 per thread) ----
    float4 v[NTILES];
    #pragma unroll
    for (int k = 0; k < NTILES; ++k) {
        const int e = k * TILE + 4 * tid;
        if (e < FRAMES) {
            v[k] = *reinterpret_cast<const float4*>(xin + e);
        } else {
            v[k] = make_float4(0.f, 0.f, 0.f, 0.f);
        }
    }

    // running carry (uniform across block)
    float cs = 0.f, cq = 0.f;

    #pragma unroll
    for (int k = 0; k < NTILES; ++k) {
        const float4 vk = v[k];

        // thread-local totals over its 4 contiguous elements
        float ts = vk.x + vk.y + vk.z + vk.w;
        float tq = vk.x * vk.x;
        tq = fmaf(vk.y, vk.y, tq);
        tq = fmaf(vk.z, vk.z, tq);
        tq = fmaf(vk.w, vk.w, tq);

        // inclusive warp scan of (ts, tq)
        float is = ts, iq = tq;
        #pragma unroll
        for (int d = 1; d < 32; d <<= 1) {
            float as = __shfl_up_sync(0xffffffffu, is, d);
            float aq = __shfl_up_sync(0xffffffffu, iq, d);
            if (lane >= d) { is += as; iq += aq; }
        }

        if (k > 0) __syncthreads();            // protect wsum reads of previous tile
        if (lane == 31) wsum[warp] = make_float2(is, iq);
        __syncthreads();

        if (warp == 0) {
            float ws = (lane < NWARPS) ? wsum[lane].x : 0.f;
            float wq = (lane < NWARPS) ? wsum[lane].y : 0.f;
            #pragma unroll
            for (int d = 1; d < NWARPS; d <<= 1) {
                float as = __shfl_up_sync(0xffffffffu, ws, d);
                float aq = __shfl_up_sync(0xffffffffu, wq, d);
                if (lane >= d) { ws += as; wq += aq; }
            }
            if (lane < NWARPS) wsum[lane] = make_float2(ws, wq);
        }
        __syncthreads();

        // exclusive prefix before this thread's 4 elements (including carry)
        const float2 wp  = (warp > 0) ? wsum[warp - 1] : make_float2(0.f, 0.f);
        const float2 tot = wsum[NWARPS - 1];
        float ps = cs + wp.x + (is - ts);
        float pq = cq + wp.y + (iq - tq);
        cs += tot.x;
        cq += tot.y;

        // ---- normalize: out = (c*x - s) * rsqrt(c*q - s^2 + eps*c^2) ----
        const int e = k * TILE + 4 * tid;
        if (e < FRAMES) {
            float r[4] = {vk.x, vk.y, vk.z, vk.w};
            float c = (float)e;
            #pragma unroll
            for (int j = 0; j < 4; ++j) {
                const float xv = r[j];
                ps += xv;
                pq  = fmaf(xv, xv, pq);
                c  += 1.f;
                const float ecc = EPS * c * c;
                const float den = fmaf(c, pq, fmaf(-ps, ps, ecc)); // c*q - s^2 + eps*c^2
                const float num = fmaf(c, xv, -ps);                // c*x - s
                r[j] = num * rsqrtf(den);
            }
            *reinterpret_cast<float4*>(xout + e) =
                make_float4(r[0], r[1], r[2], r[3]);
        }
    }
}

extern "C" void kernel_launch(void* const* d_in, const int* in_sizes, int n_in,
                              void* d_out, int out_size)
{
    const float* x = (const float*)d_in[0];
    float* outp    = (float*)d_out;
    const int rows = in_sizes[0] / FRAMES;   // 32 * 512 = 16384
    cumnorm_kernel<<<rows, THREADS>>>(x, outp);
}